// round 5
// baseline (speedup 1.0000x reference)
#include <cuda_runtime.h>
#include <cstdint>

// ProbAttention (Informer ProbSparse) — B=2, L=4096, H=8, D=64, FACTOR=5 → u=U_part=45

#define BB 2
#define LL 4096
#define HH 8
#define DD 64
#define NBH 16          // B*H
#define UU 45
#define UP 48           // padded u
#define NSPLIT 32
#define KPB (LL / NSPLIT)   // 128 keys per block
#define TIL 32
#define NTILE (KPB / TIL)   // 4
#define NSAMP (LL * UU)     // 184320

// chunked sparse-measure stage
#define NCHUNK 8
#define CROWS 512           // keys per chunk
#define CAP 32768           // bucket capacity per chunk (avg 23040)
#define KSTR 68             // padded smem row stride (floats)

__device__ int   g_idx[NSAMP];
__device__ int   g_bcnt[NCHUNK * LL];
__device__ int   g_boff[NCHUNK * (LL + 1)];
__device__ uint32_t g_blist[NCHUNK * CAP];
__device__ float g_cmax[NBH * NCHUNK * LL];
__device__ float g_csum[NBH * NCHUNK * LL];
__device__ int   g_Mtop[NBH * UU];
__device__ float g_pm[NBH * NSPLIT * UP];
__device__ float g_pl[NBH * NSPLIT * UP];
__device__ float g_pacc[NBH * NSPLIT * UP * DD];

// ---------------------------------------------------------------- threefry
__device__ __forceinline__ uint32_t rotl32(uint32_t x, int n) {
    return (x << n) | (x >> (32 - n));
}

__device__ __forceinline__ void threefry2x32(uint32_t k0, uint32_t k1,
                                             uint32_t c0, uint32_t c1,
                                             uint32_t& o0, uint32_t& o1) {
    uint32_t ks0 = k0, ks1 = k1, ks2 = k0 ^ k1 ^ 0x1BD11BDAu;
    uint32_t x0 = c0 + ks0, x1 = c1 + ks1;
#define TF_R(r) { x0 += x1; x1 = rotl32(x1, r); x1 ^= x0; }
    TF_R(13) TF_R(15) TF_R(26) TF_R(6)
    x0 += ks1; x1 += ks2 + 1u;
    TF_R(17) TF_R(29) TF_R(16) TF_R(24)
    x0 += ks2; x1 += ks0 + 2u;
    TF_R(13) TF_R(15) TF_R(26) TF_R(6)
    x0 += ks0; x1 += ks1 + 3u;
    TF_R(17) TF_R(29) TF_R(16) TF_R(24)
    x0 += ks1; x1 += ks2 + 4u;
    TF_R(13) TF_R(15) TF_R(26) TF_R(6)
    x0 += ks2; x1 += ks0 + 5u;
#undef TF_R
    o0 = x0; o1 = x1;
}

// Modern JAX partitionable threefry (verified round 3):
//   k2 = threefry((0,1),(0,1)); bits[j] = xor-fold of threefry(k2,(0,j));
//   idx[j] = bits[j] & 4095.
__global__ __launch_bounds__(256) void idx_kernel() {
    int j = blockIdx.x * 256 + threadIdx.x;
    if (j >= NSAMP) return;
    uint32_t s0, s1;
    threefry2x32(0u, 1u, 0u, 1u, s0, s1);
    uint32_t o0, o1;
    threefry2x32(s0, s1, 0u, (uint32_t)j, o0, o1);
    g_idx[j] = (int)((o0 ^ o1) & 4095u);
}

// ---------------------------------------------------------------- bucket counts
__global__ __launch_bounds__(256) void count_kernel() {
    int q = blockIdx.x * 256 + threadIdx.x;
    if (q >= LL) return;
    const int* ip = g_idx + q * UU;
    uint64_t cnt = 0;   // 8 bits per chunk, max 45
#pragma unroll
    for (int s = 0; s < UU; ++s) {
        int c = ip[s] >> 9;
        cnt += 1ull << (c * 8);
    }
#pragma unroll
    for (int c = 0; c < NCHUNK; ++c)
        g_bcnt[c * LL + q] = (int)((cnt >> (c * 8)) & 0xff);
}

// ---------------------------------------------------------------- exclusive scan per chunk
__global__ __launch_bounds__(1024) void scan_kernel() {
    __shared__ int wsum[32];
    int c = blockIdx.x;
    int t = threadIdx.x;
    int lane = t & 31, warp = t >> 5;
    int cnt[4], s = 0;
    int bq = t * 4;
#pragma unroll
    for (int j = 0; j < 4; ++j) { cnt[j] = g_bcnt[c * LL + bq + j]; s += cnt[j]; }
    int inc = s;
#pragma unroll
    for (int off = 1; off < 32; off <<= 1) {
        int v = __shfl_up_sync(0xffffffffu, inc, off);
        if (lane >= off) inc += v;
    }
    if (lane == 31) wsum[warp] = inc;
    __syncthreads();
    if (warp == 0) {
        int v = wsum[lane];
        int iv = v;
#pragma unroll
        for (int off = 1; off < 32; off <<= 1) {
            int u = __shfl_up_sync(0xffffffffu, iv, off);
            if (lane >= off) iv += u;
        }
        wsum[lane] = iv - v;
    }
    __syncthreads();
    int run = wsum[warp] + (inc - s);
#pragma unroll
    for (int j = 0; j < 4; ++j) { g_boff[c * (LL + 1) + bq + j] = run; run += cnt[j]; }
    if (t == 1023) g_boff[c * (LL + 1) + LL] = run;
}

// ---------------------------------------------------------------- fill buckets (deterministic order)
__global__ __launch_bounds__(256) void fill_kernel() {
    int q = blockIdx.x * 256 + threadIdx.x;
    if (q >= LL) return;
    int off[NCHUNK];
#pragma unroll
    for (int c = 0; c < NCHUNK; ++c) off[c] = g_boff[c * (LL + 1) + q];
    const int* ip = g_idx + q * UU;
#pragma unroll 1
    for (int s = 0; s < UU; ++s) {
        int idx = ip[s];
        int c = idx >> 9;
        g_blist[c * CAP + off[c]++] = ((uint32_t)q << 12) | (uint32_t)idx;
    }
}

// ---------------------------------------------------------------- chunked sparse measure
// block = (bh, chunk); K chunk cached in smem; warps walk contiguous q-sorted bucket slices.
__global__ __launch_bounds__(512) void mchunk_kernel(const float* __restrict__ Q,
                                                     const float* __restrict__ K) {
    extern __shared__ float sK[];   // CROWS x KSTR
    int bh = blockIdx.x >> 3;
    int c  = blockIdx.x & 7;
    int b = bh >> 3, h = bh & 7;
    int t = threadIdx.x;

    // load K chunk (512 rows x 64 floats), coalesced
#pragma unroll
    for (int i = 0; i < 16; ++i) {
        int f = i * 512 + t;
        int row = f >> 4, c4 = f & 15;
        float4 v = *(const float4*)(K + ((size_t)((b * LL + c * CROWS + row)) * HH + h) * DD + c4 * 4);
        *(float4*)&sK[row * KSTR + c4 * 4] = v;
    }
    __syncthreads();

    int warp = t >> 5, lane = t & 31;
    int slot = lane >> 3, l8 = lane & 7;
    int q0 = warp * 256;                        // 16 warps x 256 q
    float* cmaxp = g_cmax + (size_t)(bh * NCHUNK + c) * LL;
    float* csump = g_csum + (size_t)(bh * NCHUNK + c) * LL;

    // defaults for q with no samples in this chunk
    for (int j = lane; j < 256; j += 32) {
        cmaxp[q0 + j] = -3.4e38f;
        csump[q0 + j] = 0.f;
    }
    __syncwarp();

    int beg = g_boff[c * (LL + 1) + q0];
    int end = g_boff[c * (LL + 1) + q0 + 256];
    const uint32_t* list = g_blist + c * CAP;
    const float* qbase = Q + ((size_t)(b * LL) * HH + h) * DD + l8 * 8;

    int curq = -1;
    float mx = -3.4e38f, sm = 0.f;
#pragma unroll 1
    for (int e = beg; e < end; e += 4) {
        int n4 = end - e; if (n4 > 4) n4 = 4;
        uint32_t ent[4];
#pragma unroll
        for (int k = 0; k < 4; ++k) ent[k] = list[e + ((k < n4) ? k : 0)];
        uint32_t my = ent[(slot < n4) ? slot : 0];
        int qk  = (int)(my >> 12);
        int row = (int)(my & 511u);
        const float* qp = qbase + (size_t)qk * (HH * DD);
        float4 qa = *(const float4*)qp;
        float4 qb = *(const float4*)(qp + 4);
        float4 ka = *(const float4*)&sK[row * KSTR + l8 * 8];
        float4 kb = *(const float4*)&sK[row * KSTR + l8 * 8 + 4];
        float p = qa.x * ka.x + qa.y * ka.y + qa.z * ka.z + qa.w * ka.w
                + qb.x * kb.x + qb.y * kb.y + qb.z * kb.z + qb.w * kb.w;
        p += __shfl_xor_sync(0xffffffffu, p, 1);
        p += __shfl_xor_sync(0xffffffffu, p, 2);
        p += __shfl_xor_sync(0xffffffffu, p, 4);
        float pk[4];
#pragma unroll
        for (int k = 0; k < 4; ++k) pk[k] = __shfl_sync(0xffffffffu, p, k * 8);
#pragma unroll
        for (int k = 0; k < 4; ++k) {
            if (k < n4) {
                int qq = (int)(ent[k] >> 12);
                if (qq != curq) {
                    if (lane == 0 && curq >= 0) { cmaxp[curq] = mx; csump[curq] = sm; }
                    curq = qq; mx = pk[k]; sm = pk[k];
                } else {
                    mx = fmaxf(mx, pk[k]); sm += pk[k];
                }
            }
        }
    }
    if (lane == 0 && curq >= 0) { cmaxp[curq] = mx; csump[curq] = sm; }
}

// ---------------------------------------------------------------- stable top-45 (folds chunk reduce)
__global__ __launch_bounds__(1024) void topk_kernel() {
    __shared__ float wv[32];
    __shared__ int   wi[32];
    __shared__ int   s_win;
    int bh = blockIdx.x;
    int t = threadIdx.x;
    int lane = t & 31, warp = t >> 5;
    const float NEG_INF = -3.4e38f;

    float v[4];
    int base = t * 4;
#pragma unroll
    for (int j = 0; j < 4; ++j) {
        int q = base + j;
        float mxv = NEG_INF, sum = 0.f;
#pragma unroll
        for (int c = 0; c < NCHUNK; ++c) {
            mxv = fmaxf(mxv, g_cmax[(size_t)(bh * NCHUNK + c) * LL + q]);
            sum += g_csum[(size_t)(bh * NCHUNK + c) * LL + q];
        }
        v[j] = mxv - sum * (1.0f / LL);
    }
    int removed = 0;

    for (int p = 0; p < UU; ++p) {
        float bv = NEG_INF;
        int   bi = 0x7fffffff;
#pragma unroll
        for (int j = 0; j < 4; ++j) {
            if (!((removed >> j) & 1)) {
                float vj = v[j];
                if (vj > bv) { bv = vj; bi = base + j; }
            }
        }
#pragma unroll
        for (int off = 16; off > 0; off >>= 1) {
            float ov = __shfl_xor_sync(0xffffffffu, bv, off);
            int   oi = __shfl_xor_sync(0xffffffffu, bi, off);
            if (ov > bv || (ov == bv && oi < bi)) { bv = ov; bi = oi; }
        }
        if (lane == 0) { wv[warp] = bv; wi[warp] = bi; }
        __syncthreads();
        if (warp == 0) {
            float fv = wv[lane];
            int   fi = wi[lane];
#pragma unroll
            for (int off = 16; off > 0; off >>= 1) {
                float ov = __shfl_xor_sync(0xffffffffu, fv, off);
                int   oi = __shfl_xor_sync(0xffffffffu, fi, off);
                if (ov > fv || (ov == fv && oi < fi)) { fv = ov; fi = oi; }
            }
            if (lane == 0) {
                g_Mtop[bh * UU + p] = fi;
                s_win = fi;
            }
        }
        __syncthreads();
        int win = s_win;
        if ((win >> 2) == t) removed |= 1 << (win & 3);
    }
}

// ---------------------------------------------------------------- split-K flash attention
__global__ __launch_bounds__(256) void attn_kernel(const float* __restrict__ Q,
                                                   const float* __restrict__ K,
                                                   const float* __restrict__ V,
                                                   const int*   __restrict__ amask) {
    __shared__ float Qs[UP][68];
    __shared__ float Ks[TIL][68];
    __shared__ float Vs[TIL][68];
    __shared__ float Ss[UP][36];
    __shared__ float smm[UP], sml[UP], sma[UP];

    int bh = blockIdx.x / NSPLIT;
    int sp = blockIdx.x % NSPLIT;
    int b = bh >> 3, h = bh & 7;
    int t = threadIdx.x;
    int tx = t & 15, ty = t >> 4;
    int u0 = ty * 3;

    for (int i = t; i < UP * DD; i += 256) {
        int u = i >> 6, d = i & 63;
        float v = 0.f;
        if (u < UU) {
            int qi = g_Mtop[bh * UU + u];
            v = Q[((size_t)(b * LL + qi) * HH + h) * DD + d] * 0.125f;  // 1/sqrt(64)
        }
        Qs[u][d] = v;
    }
    if (t < UP) { smm[t] = -1e30f; sml[t] = 0.f; }

    float4 acc[3];
    acc[0] = make_float4(0.f, 0.f, 0.f, 0.f);
    acc[1] = acc[0]; acc[2] = acc[0];
    __syncthreads();

    int j0base = sp * KPB;
#pragma unroll 1
    for (int tile = 0; tile < NTILE; ++tile) {
        int j0 = j0base + tile * TIL;
        {
            const float* kb = K + ((size_t)(b * LL + j0) * HH + h) * DD;
            const float* vb = V + ((size_t)(b * LL + j0) * HH + h) * DD;
#pragma unroll
            for (int r = 0; r < 2; ++r) {
                int idx = t + 256 * r;
                int j = idx >> 4, c4 = idx & 15;
                *(float4*)&Ks[j][c4 * 4] = *(const float4*)(kb + (size_t)j * (HH * DD) + c4 * 4);
                *(float4*)&Vs[j][c4 * 4] = *(const float4*)(vb + (size_t)j * (HH * DD) + c4 * 4);
            }
        }
        __syncthreads();

        float s[3][2] = {};
#pragma unroll
        for (int d4 = 0; d4 < 16; ++d4) {
            float4 kv0 = *(const float4*)&Ks[tx][d4 * 4];
            float4 kv1 = *(const float4*)&Ks[tx + 16][d4 * 4];
#pragma unroll
            for (int uu = 0; uu < 3; ++uu) {
                float4 qv = *(const float4*)&Qs[u0 + uu][d4 * 4];
                s[uu][0] += qv.x * kv0.x + qv.y * kv0.y + qv.z * kv0.z + qv.w * kv0.w;
                s[uu][1] += qv.x * kv1.x + qv.y * kv1.y + qv.z * kv1.z + qv.w * kv1.w;
            }
        }
#pragma unroll
        for (int jj = 0; jj < 2; ++jj) {
            int jl = tx + 16 * jj;
            int mk = amask[b * LL + j0 + jl];
#pragma unroll
            for (int uu = 0; uu < 3; ++uu)
                Ss[u0 + uu][jl] = mk ? s[uu][jj] : -1e30f;
        }
        __syncthreads();

        if (t < UP) {
            int u = t;
            float mold = smm[u];
            float mnew = mold;
#pragma unroll
            for (int j = 0; j < TIL; ++j) mnew = fmaxf(mnew, Ss[u][j]);
            float alpha = __expf(mold - mnew);
            float lsum = 0.f;
#pragma unroll
            for (int j = 0; j < TIL; ++j) {
                float e = __expf(Ss[u][j] - mnew);
                Ss[u][j] = e;
                lsum += e;
            }
            sml[u] = sml[u] * alpha + lsum;
            smm[u] = mnew;
            sma[u] = alpha;
        }
        __syncthreads();

#pragma unroll
        for (int uu = 0; uu < 3; ++uu) {
            float a = sma[u0 + uu];
            acc[uu].x *= a; acc[uu].y *= a; acc[uu].z *= a; acc[uu].w *= a;
        }
#pragma unroll
        for (int j4 = 0; j4 < TIL / 4; ++j4) {
            float4 vr0 = *(const float4*)&Vs[j4 * 4 + 0][tx * 4];
            float4 vr1 = *(const float4*)&Vs[j4 * 4 + 1][tx * 4];
            float4 vr2 = *(const float4*)&Vs[j4 * 4 + 2][tx * 4];
            float4 vr3 = *(const float4*)&Vs[j4 * 4 + 3][tx * 4];
#pragma unroll
            for (int uu = 0; uu < 3; ++uu) {
                float4 sv = *(const float4*)&Ss[u0 + uu][j4 * 4];
                acc[uu].x += sv.x * vr0.x + sv.y * vr1.x + sv.z * vr2.x + sv.w * vr3.x;
                acc[uu].y += sv.x * vr0.y + sv.y * vr1.y + sv.z * vr2.y + sv.w * vr3.y;
                acc[uu].z += sv.x * vr0.z + sv.y * vr1.z + sv.z * vr2.z + sv.w * vr3.z;
                acc[uu].w += sv.x * vr0.w + sv.y * vr1.w + sv.z * vr2.w + sv.w * vr3.w;
            }
        }
        __syncthreads();
    }

    size_t base = (size_t)(bh * NSPLIT + sp) * UP;
#pragma unroll
    for (int uu = 0; uu < 3; ++uu)
        *(float4*)&g_pacc[(base + u0 + uu) * DD + tx * 4] = acc[uu];
    if (t < UP) { g_pm[base + t] = smm[t]; g_pl[base + t] = sml[t]; }
}

// ---------------------------------------------------------------- combine split-K partials
__global__ __launch_bounds__(256) void combine_kernel(float* __restrict__ out) {
    int w = blockIdx.x * 8 + ((int)threadIdx.x >> 5);
    if (w >= NBH * UU) return;
    int lane = threadIdx.x & 31;
    int bh = w / UU, u = w % UU;
    int b = bh >> 3, h = bh & 7;

    float m = -3.4e38f;
#pragma unroll 8
    for (int i = 0; i < NSPLIT; ++i)
        m = fmaxf(m, g_pm[(bh * NSPLIT + i) * UP + u]);

    float Lsum = 0.f, o0 = 0.f, o1 = 0.f;
#pragma unroll 4
    for (int i = 0; i < NSPLIT; ++i) {
        size_t pb = (size_t)(bh * NSPLIT + i) * UP + u;
        float wgt = __expf(g_pm[pb] - m);
        Lsum += g_pl[pb] * wgt;
        o0 += g_pacc[pb * DD + lane] * wgt;
        o1 += g_pacc[pb * DD + lane + 32] * wgt;
    }
    float inv = 1.0f / Lsum;
    size_t ob = ((size_t)(b * UU + u) * HH + h) * DD;
    out[ob + lane]      = o0 * inv;
    out[ob + lane + 32] = o1 * inv;
}

// ----------------------------------------------------------------
extern "C" void kernel_launch(void* const* d_in, const int* in_sizes, int n_in,
                              void* d_out, int out_size) {
    const float* Q    = (const float*)d_in[0];
    const float* K    = (const float*)d_in[1];
    const float* V    = (const float*)d_in[2];
    const int*   mask = (const int*)d_in[3];
    float* out = (float*)d_out;

    const int mchunk_smem = CROWS * KSTR * 4;   // 139264 B
    cudaFuncSetAttribute(mchunk_kernel, cudaFuncAttributeMaxDynamicSharedMemorySize, mchunk_smem);

    idx_kernel<<<(NSAMP + 255) / 256, 256>>>();
    count_kernel<<<LL / 256, 256>>>();
    scan_kernel<<<NCHUNK, 1024>>>();
    fill_kernel<<<LL / 256, 256>>>();
    mchunk_kernel<<<NBH * NCHUNK, 512, mchunk_smem>>>(Q, K);
    topk_kernel<<<NBH, 1024>>>();
    attn_kernel<<<NBH * NSPLIT, 256>>>(Q, K, V, mask);
    combine_kernel<<<(NBH * UU + 7) / 8, 256>>>(out);
}

// round 6
// speedup vs baseline: 2.3035x; 2.3035x over previous
#include <cuda_runtime.h>
#include <cstdint>

// ProbAttention (Informer ProbSparse) — B=2, L=4096, H=8, D=64, FACTOR=5 → u=U_part=45

#define BB 2
#define LL 4096
#define HH 8
#define DD 64
#define NBH 16          // B*H
#define UU 45
#define UP 48           // padded u
#define NSPLIT 32
#define KPB (LL / NSPLIT)   // 128 keys per block
#define TIL 32
#define NTILE (KPB / TIL)   // 4
#define NSAMP (LL * UU)     // 184320

__device__ int   g_idx[NSAMP];
__device__ float g_M[NBH * LL];
__device__ int   g_Mtop[NBH * UU];
__device__ float g_pm[NBH * NSPLIT * UP];
__device__ float g_pl[NBH * NSPLIT * UP];
__device__ float g_pacc[NBH * NSPLIT * UP * DD];

// ---------------------------------------------------------------- threefry
__device__ __forceinline__ uint32_t rotl32(uint32_t x, int n) {
    return (x << n) | (x >> (32 - n));
}

__device__ __forceinline__ void threefry2x32(uint32_t k0, uint32_t k1,
                                             uint32_t c0, uint32_t c1,
                                             uint32_t& o0, uint32_t& o1) {
    uint32_t ks0 = k0, ks1 = k1, ks2 = k0 ^ k1 ^ 0x1BD11BDAu;
    uint32_t x0 = c0 + ks0, x1 = c1 + ks1;
#define TF_R(r) { x0 += x1; x1 = rotl32(x1, r); x1 ^= x0; }
    TF_R(13) TF_R(15) TF_R(26) TF_R(6)
    x0 += ks1; x1 += ks2 + 1u;
    TF_R(17) TF_R(29) TF_R(16) TF_R(24)
    x0 += ks2; x1 += ks0 + 2u;
    TF_R(13) TF_R(15) TF_R(26) TF_R(6)
    x0 += ks0; x1 += ks1 + 3u;
    TF_R(17) TF_R(29) TF_R(16) TF_R(24)
    x0 += ks1; x1 += ks2 + 4u;
    TF_R(13) TF_R(15) TF_R(26) TF_R(6)
    x0 += ks2; x1 += ks0 + 5u;
#undef TF_R
    o0 = x0; o1 = x1;
}

// Modern JAX partitionable threefry (verified round 3):
//   k2 = threefry((0,1),(0,1)); bits[j] = xor-fold of threefry(k2,(0,j));
//   idx[j] = bits[j] & 4095 (span 4096 is a power of two -> multiplier vanishes).
__global__ __launch_bounds__(256) void idx_kernel() {
    int j = blockIdx.x * 256 + threadIdx.x;
    if (j >= NSAMP) return;
    uint32_t s0, s1;
    threefry2x32(0u, 1u, 0u, 1u, s0, s1);
    uint32_t o0, o1;
    threefry2x32(s0, s1, 0u, (uint32_t)j, o0, o1);
    g_idx[j] = (int)((o0 ^ o1) & 4095u);
}

// ---------------------------------------------------------------- sparse measure M
// one warp per (b,h,q); 4 groups of 8 lanes; 4 samples per group per iter (16 loads in flight)
__global__ __launch_bounds__(256) void m_kernel(const float* __restrict__ Q,
                                                const float* __restrict__ K) {
    int w    = blockIdx.x * 8 + (threadIdx.x >> 5);
    int lane = threadIdx.x & 31;
    int bh = w >> 12;
    int q  = w & 4095;
    int b = bh >> 3, h = bh & 7;
    int g = lane >> 3, l8 = lane & 7;

    const float* qp = Q + ((size_t)(b * LL + q) * HH + h) * DD + l8 * 8;
    float4 qa = *(const float4*)qp;
    float4 qb = *(const float4*)(qp + 4);
    const float* kbase = K + ((size_t)(b * LL) * HH + h) * DD + l8 * 8;
    const int* idxp = g_idx + q * UU;

    float mx = -3.4e38f, sm = 0.f;
    // 3 iters x 4 groups x 4 samples = 48 slots >= 45
#pragma unroll 1
    for (int t = 0; t < 3; ++t) {
        int sb = t * 16 + g;
        float p[4];
        bool vv[4];
#pragma unroll
        for (int k = 0; k < 4; ++k) {
            int s = sb + k * 4;
            vv[k] = (s < UU);
            int i = vv[k] ? idxp[s] : 0;
            const float* kp = kbase + (size_t)i * (HH * DD);
            float4 ka = *(const float4*)kp;
            float4 kb = *(const float4*)(kp + 4);
            p[k] = qa.x * ka.x + qa.y * ka.y + qa.z * ka.z + qa.w * ka.w
                 + qb.x * kb.x + qb.y * kb.y + qb.z * kb.z + qb.w * kb.w;
        }
#pragma unroll
        for (int k = 0; k < 4; ++k) p[k] += __shfl_xor_sync(0xffffffffu, p[k], 1);
#pragma unroll
        for (int k = 0; k < 4; ++k) p[k] += __shfl_xor_sync(0xffffffffu, p[k], 2);
#pragma unroll
        for (int k = 0; k < 4; ++k) p[k] += __shfl_xor_sync(0xffffffffu, p[k], 4);
#pragma unroll
        for (int k = 0; k < 4; ++k)
            if (vv[k]) { mx = fmaxf(mx, p[k]); sm += p[k]; }
    }
    mx = fmaxf(mx, __shfl_xor_sync(0xffffffffu, mx, 8));
    sm +=           __shfl_xor_sync(0xffffffffu, sm, 8);
    mx = fmaxf(mx, __shfl_xor_sync(0xffffffffu, mx, 16));
    sm +=           __shfl_xor_sync(0xffffffffu, sm, 16);
    if (lane == 0) g_M[bh * LL + q] = mx - sm * (1.0f / LL);
}

// ---------------------------------------------------------------- stable top-45
// 1024 threads, 4 values in registers; 2 barriers per pass.
__global__ __launch_bounds__(1024) void topk_kernel() {
    __shared__ float wv[32];
    __shared__ int   wi[32];
    __shared__ int   s_win;
    int bh = blockIdx.x;
    int t = threadIdx.x;
    int lane = t & 31, warp = t >> 5;
    const float NEG_INF = -3.4e38f;

    float v[4];
    int base = t * 4;
#pragma unroll
    for (int j = 0; j < 4; ++j) v[j] = g_M[bh * LL + base + j];
    int removed = 0;

    for (int p = 0; p < UU; ++p) {
        float bv = NEG_INF;
        int   bi = 0x7fffffff;
#pragma unroll
        for (int j = 0; j < 4; ++j) {
            if (!((removed >> j) & 1)) {
                float vj = v[j];
                if (vj > bv) { bv = vj; bi = base + j; }   // ascending j keeps smallest idx on ties
            }
        }
#pragma unroll
        for (int off = 16; off > 0; off >>= 1) {
            float ov = __shfl_xor_sync(0xffffffffu, bv, off);
            int   oi = __shfl_xor_sync(0xffffffffu, bi, off);
            if (ov > bv || (ov == bv && oi < bi)) { bv = ov; bi = oi; }
        }
        if (lane == 0) { wv[warp] = bv; wi[warp] = bi; }
        __syncthreads();
        if (warp == 0) {
            float fv = wv[lane];
            int   fi = wi[lane];
#pragma unroll
            for (int off = 16; off > 0; off >>= 1) {
                float ov = __shfl_xor_sync(0xffffffffu, fv, off);
                int   oi = __shfl_xor_sync(0xffffffffu, fi, off);
                if (ov > fv || (ov == fv && oi < fi)) { fv = ov; fi = oi; }
            }
            if (lane == 0) {
                g_Mtop[bh * UU + p] = fi;
                s_win = fi;
            }
        }
        __syncthreads();
        int win = s_win;
        if ((win >> 2) == t) removed |= 1 << (win & 3);
    }
}

// ---------------------------------------------------------------- split-K flash attention
// block: (b,h, key-split). 256 thr = 16x16; thread owns 3 u-rows x (2 keys | 4 dims)
__global__ __launch_bounds__(256) void attn_kernel(const float* __restrict__ Q,
                                                   const float* __restrict__ K,
                                                   const float* __restrict__ V,
                                                   const int*   __restrict__ amask) {
    __shared__ float Qs[UP][68];
    __shared__ float Ks[TIL][68];
    __shared__ float Vs[TIL][68];
    __shared__ float Ss[UP][36];
    __shared__ float smm[UP], sml[UP], sma[UP];

    int bh = blockIdx.x / NSPLIT;
    int sp = blockIdx.x % NSPLIT;
    int b = bh >> 3, h = bh & 7;
    int t = threadIdx.x;
    int tx = t & 15, ty = t >> 4;
    int u0 = ty * 3;

    for (int i = t; i < UP * DD; i += 256) {
        int u = i >> 6, d = i & 63;
        float v = 0.f;
        if (u < UU) {
            int qi = g_Mtop[bh * UU + u];
            v = Q[((size_t)(b * LL + qi) * HH + h) * DD + d] * 0.125f;  // 1/sqrt(64)
        }
        Qs[u][d] = v;
    }
    if (t < UP) { smm[t] = -1e30f; sml[t] = 0.f; }

    float4 acc[3];
    acc[0] = make_float4(0.f, 0.f, 0.f, 0.f);
    acc[1] = acc[0]; acc[2] = acc[0];
    __syncthreads();

    int j0base = sp * KPB;
#pragma unroll 1
    for (int tile = 0; tile < NTILE; ++tile) {
        int j0 = j0base + tile * TIL;
        {
            const float* kb = K + ((size_t)(b * LL + j0) * HH + h) * DD;
            const float* vb = V + ((size_t)(b * LL + j0) * HH + h) * DD;
#pragma unroll
            for (int r = 0; r < 2; ++r) {
                int idx = t + 256 * r;     // 0..511 float4s of a 32x64 tile
                int j = idx >> 4, c4 = idx & 15;
                *(float4*)&Ks[j][c4 * 4] = *(const float4*)(kb + (size_t)j * (HH * DD) + c4 * 4);
                *(float4*)&Vs[j][c4 * 4] = *(const float4*)(vb + (size_t)j * (HH * DD) + c4 * 4);
            }
        }
        __syncthreads();

        // scores: 3u x 2j per thread (j = tx, tx+16)
        float s[3][2] = {};
#pragma unroll
        for (int d4 = 0; d4 < 16; ++d4) {
            float4 kv0 = *(const float4*)&Ks[tx][d4 * 4];
            float4 kv1 = *(const float4*)&Ks[tx + 16][d4 * 4];
#pragma unroll
            for (int uu = 0; uu < 3; ++uu) {
                float4 qv = *(const float4*)&Qs[u0 + uu][d4 * 4];
                s[uu][0] += qv.x * kv0.x + qv.y * kv0.y + qv.z * kv0.z + qv.w * kv0.w;
                s[uu][1] += qv.x * kv1.x + qv.y * kv1.y + qv.z * kv1.z + qv.w * kv1.w;
            }
        }
#pragma unroll
        for (int jj = 0; jj < 2; ++jj) {
            int jl = tx + 16 * jj;
            int mk = amask[b * LL + j0 + jl];
#pragma unroll
            for (int uu = 0; uu < 3; ++uu)
                Ss[u0 + uu][jl] = mk ? s[uu][jj] : -1e30f;
        }
        __syncthreads();

        // online softmax row update (one thread per u-row)
        if (t < UP) {
            int u = t;
            float mold = smm[u];
            float mnew = mold;
#pragma unroll
            for (int j = 0; j < TIL; ++j) mnew = fmaxf(mnew, Ss[u][j]);
            float alpha = __expf(mold - mnew);
            float lsum = 0.f;
#pragma unroll
            for (int j = 0; j < TIL; ++j) {
                float e = __expf(Ss[u][j] - mnew);
                Ss[u][j] = e;
                lsum += e;
            }
            sml[u] = sml[u] * alpha + lsum;
            smm[u] = mnew;
            sma[u] = alpha;
        }
        __syncthreads();

        // rescale + P@V: thread owns (3u, d=4*tx..4*tx+3)
#pragma unroll
        for (int uu = 0; uu < 3; ++uu) {
            float a = sma[u0 + uu];
            acc[uu].x *= a; acc[uu].y *= a; acc[uu].z *= a; acc[uu].w *= a;
        }
#pragma unroll
        for (int j4 = 0; j4 < TIL / 4; ++j4) {
            float4 vr0 = *(const float4*)&Vs[j4 * 4 + 0][tx * 4];
            float4 vr1 = *(const float4*)&Vs[j4 * 4 + 1][tx * 4];
            float4 vr2 = *(const float4*)&Vs[j4 * 4 + 2][tx * 4];
            float4 vr3 = *(const float4*)&Vs[j4 * 4 + 3][tx * 4];
#pragma unroll
            for (int uu = 0; uu < 3; ++uu) {
                float4 sv = *(const float4*)&Ss[u0 + uu][j4 * 4];
                acc[uu].x += sv.x * vr0.x + sv.y * vr1.x + sv.z * vr2.x + sv.w * vr3.x;
                acc[uu].y += sv.x * vr0.y + sv.y * vr1.y + sv.z * vr2.y + sv.w * vr3.y;
                acc[uu].z += sv.x * vr0.z + sv.y * vr1.z + sv.z * vr2.z + sv.w * vr3.z;
                acc[uu].w += sv.x * vr0.w + sv.y * vr1.w + sv.z * vr2.w + sv.w * vr3.w;
            }
        }
        __syncthreads();
    }

    size_t base = (size_t)(bh * NSPLIT + sp) * UP;
#pragma unroll
    for (int uu = 0; uu < 3; ++uu)
        *(float4*)&g_pacc[(base + u0 + uu) * DD + tx * 4] = acc[uu];
    if (t < UP) { g_pm[base + t] = smm[t]; g_pl[base + t] = sml[t]; }
}

// ---------------------------------------------------------------- combine split-K partials
__global__ __launch_bounds__(256) void combine_kernel(float* __restrict__ out) {
    int w = blockIdx.x * 8 + ((int)threadIdx.x >> 5);
    if (w >= NBH * UU) return;
    int lane = threadIdx.x & 31;
    int bh = w / UU, u = w % UU;
    int b = bh >> 3, h = bh & 7;

    float m = -3.4e38f;
#pragma unroll 8
    for (int i = 0; i < NSPLIT; ++i)
        m = fmaxf(m, g_pm[(bh * NSPLIT + i) * UP + u]);

    float Lsum = 0.f, o0 = 0.f, o1 = 0.f;
#pragma unroll 4
    for (int i = 0; i < NSPLIT; ++i) {
        size_t pb = (size_t)(bh * NSPLIT + i) * UP + u;
        float wgt = __expf(g_pm[pb] - m);
        Lsum += g_pl[pb] * wgt;
        o0 += g_pacc[pb * DD + lane] * wgt;
        o1 += g_pacc[pb * DD + lane + 32] * wgt;
    }
    float inv = 1.0f / Lsum;
    size_t ob = ((size_t)(b * UU + u) * HH + h) * DD;
    out[ob + lane]      = o0 * inv;
    out[ob + lane + 32] = o1 * inv;
}

// ----------------------------------------------------------------
extern "C" void kernel_launch(void* const* d_in, const int* in_sizes, int n_in,
                              void* d_out, int out_size) {
    const float* Q    = (const float*)d_in[0];
    const float* K    = (const float*)d_in[1];
    const float* V    = (const float*)d_in[2];
    const int*   mask = (const int*)d_in[3];
    float* out = (float*)d_out;

    idx_kernel<<<(NSAMP + 255) / 256, 256>>>();
    m_kernel<<<NBH * LL / 8, 256>>>(Q, K);
    topk_kernel<<<NBH, 1024>>>();
    attn_kernel<<<NBH * NSPLIT, 256>>>(Q, K, V, mask);
    combine_kernel<<<(NBH * UU + 7) / 8, 256>>>(out);
}